// round 4
// baseline (speedup 1.0000x reference)
#include <cuda_runtime.h>

// SimplePatchScorer: out[b, j] = dot(W, permuted_patch_row(b, j)) + bias
//   x: (512, 3, 224, 224) fp32, W: (1,768), b: (1,) -> out: (512, 196)
//
// flat[u], u = s*588 + v; s = ph*16+pw in [0,256); v = c*196 + hn*14 + wn.
// out[b,j] = sum_t W[t]*flat[768j+t] + bias.
// lcm(588,768)=37632 => 4 groups/image (s in [64g,64g+64), j in [49g,49g+49)).
//
// v2: process channels sequentially. Per channel, each CTA buffers a
// [64 s'] x [196 v-local] tile (50.4 KB) and accumulates partial dots into
// persistent register accumulators. 53.5 KB smem -> 4 CTAs/SM, 100% occ,
// cross-CTA phase overlap.

#define VPAD2   197            // 196 + 1 pad (stride mod 32 = 5, coprime)
#define THREADS 512

__global__ __launch_bounds__(THREADS, 1)
void patch_scorer_v2(const float* __restrict__ x,
                     const float* __restrict__ W,
                     const float* __restrict__ bias,
                     float* __restrict__ out)
{
    extern __shared__ float smem[];
    float* Y  = smem;                 // [64][197]
    float* Ws = smem + 64 * VPAD2;    // [768]

    const int tid  = threadIdx.x;
    const int g    = blockIdx.x & 3;
    const int b    = blockIdx.x >> 2;
    const int lane = tid & 31;
    const int warp = tid >> 5;        // 16 warps

    const float* xb = x + (size_t)b * (3 * 224 * 224);

    if (tid < 384)
        ((float2*)Ws)[tid] = ((const float2*)W)[tid];
    // (covered by the phase-1 __syncthreads before first phase-2 read)

    float acc0 = 0.f, acc1 = 0.f, acc2 = 0.f, acc3 = 0.f;

    #pragma unroll
    for (int c = 0; c < 3; c++) {
        const float* xc = xb + c * (224 * 224);

        // ---- Phase 1: coalesced stream of channel-c region -> smem tile ----
        // region: hn in [0,14), phl in [0,4) (ph = 4g+phl), w in [0,224)
        // float4 index e4 in [0,3136): r = e4/56 (phl=r&3, hn=r>>2), w=4*(e4%56)
        #pragma unroll 2
        for (int e4 = tid; e4 < 3136; e4 += THREADS) {
            int w4  = e4 % 56;
            int r   = e4 / 56;
            int phl = r & 3;
            int hn  = r >> 2;
            int w   = w4 << 2;

            float4 val = *(const float4*)(xc + (hn * 16 + 4 * g + phl) * 224 + w);

            int pw = w & 15;            // 0,4,8,12 (4 lanes stay in same wn)
            int wn = w >> 4;
            int sp = phl * 16 + pw;     // s' base; val.{x,y,z,w} -> sp+0..3
            float* dst = &Y[sp * VPAD2 + hn * 14 + wn];
            dst[0 * VPAD2] = val.x;
            dst[1 * VPAD2] = val.y;
            dst[2 * VPAD2] = val.z;
            dst[3 * VPAD2] = val.w;
        }
        __syncthreads();

        // ---- Phase 2: partial dot for this channel's v-interval ----
        // row jl: u' in [768jl, 768jl+768); per s' row, v-interval intersected
        // with [196c, 196c+196); t = u' - 768jl indexes Ws contiguously.
        const int cvlo = 196 * c, cvhi = cvlo + 196;
        #pragma unroll
        for (int i = 0; i < 4; i++) {
            int jl = warp + 16 * i;
            if (jl < 49) {
                float a = 0.f;
                int ulo = 768 * jl, uhi = ulo + 768;
                int s0  = (unsigned)ulo / 588u;
                for (int sp = s0; sp < 64 && sp * 588 < uhi; sp++) {
                    int rowbase = sp * 588;
                    int alo = max(ulo, rowbase);
                    int ahi = min(uhi, rowbase + 588);
                    int vlo = max(alo - rowbase, cvlo);
                    int vhi = min(ahi - rowbase, cvhi);
                    if (vlo < vhi) {
                        const float* Wr = &Ws[rowbase + vlo - ulo];
                        const float* Yr = &Y[sp * VPAD2 + (vlo - cvlo)];
                        int len = vhi - vlo;
                        for (int k = lane; k < len; k += 32)
                            a += Wr[k] * Yr[k];
                    }
                }
                if (i == 0) acc0 += a;
                else if (i == 1) acc1 += a;
                else if (i == 2) acc2 += a;
                else acc3 += a;
            }
        }
        __syncthreads();
    }

    // ---- final warp reductions + store (bias added here) ----
    const float bv = __ldg(bias);
    float accs[4] = {acc0, acc1, acc2, acc3};
    #pragma unroll
    for (int i = 0; i < 4; i++) {
        int jl = warp + 16 * i;
        if (jl < 49) {
            float a = accs[i];
            #pragma unroll
            for (int off = 16; off; off >>= 1)
                a += __shfl_xor_sync(0xffffffffu, a, off);
            if (lane == 0)
                out[b * 196 + 49 * g + jl] = a + bv;
        }
    }
}

extern "C" void kernel_launch(void* const* d_in, const int* in_sizes, int n_in,
                              void* d_out, int out_size)
{
    const float* x  = (const float*)d_in[0];
    const float* W  = (const float*)d_in[1];
    const float* bb = (const float*)d_in[2];
    float* out = (float*)d_out;

    const int smem_bytes = (64 * VPAD2 + 768) * sizeof(float);  // ~53.5 KB
    cudaFuncSetAttribute(patch_scorer_v2,
                         cudaFuncAttributeMaxDynamicSharedMemorySize, smem_bytes);

    patch_scorer_v2<<<512 * 4, THREADS, smem_bytes>>>(x, W, bb, out);
}

// round 5
// speedup vs baseline: 1.8755x; 1.8755x over previous
#include <cuda_runtime.h>

// SimplePatchScorer: out[b, j] = dot(W, permuted_patch_row(b, j)) + bias
//   x: (512, 3, 224, 224) fp32, W: (1,768), b: (1,) -> out: (512, 196)
//
// flat[u], u = s*588 + v; s = ph*16+pw in [0,256); v = c*196 + hn*14 + wn.
// out[b,j] = sum_t W[t]*flat[768j+t] + bias.
// lcm(588,768)=37632 => 4 groups/image: s in [64g,64g+64), j in [49g,49g+49).
//
// v3: per CTA (b,g), process the 64 s' rows in TWO phl-aligned halves of 32
// (smem tile 32x589 = 75.4 KB + W => 78.5 KB, regs <=64 via launch_bounds)
// -> 2 CTAs/SM, 50% occupancy, cross-CTA phase overlap. Row accumulators
// persist in registers across halves (row 24 straddles the split).

#define VPAD    589            // 588 + 1 (bank stride 13, coprime with 32)
#define HALF_U  18816          // 32 * 588
#define THREADS 512

__global__ __launch_bounds__(THREADS, 2)
void patch_scorer_v3(const float* __restrict__ x,
                     const float* __restrict__ W,
                     const float* __restrict__ bias,
                     float* __restrict__ out)
{
    extern __shared__ float smem[];
    float* Y  = smem;               // [32][589]
    float* Ws = smem + 32 * VPAD;   // [768]

    const int tid  = threadIdx.x;
    const int g    = blockIdx.x & 3;
    const int b    = blockIdx.x >> 2;
    const int lane = tid & 31;
    const int warp = tid >> 5;      // 16 warps

    const float* xb = x + (size_t)b * (3 * 224 * 224);

    if (tid < 384)
        ((float2*)Ws)[tid] = ((const float2*)W)[tid];
    // covered by the __syncthreads() before the first phase-2 read

    float acc0 = 0.f, acc1 = 0.f, acc2 = 0.f, acc3 = 0.f;

    #pragma unroll
    for (int h2 = 0; h2 < 2; h2++) {
        if (h2) __syncthreads();    // protect Y before overwrite (2nd half)

        // ---- Phase 1: stream half's region -> smem tile (coalesced) ----
        // s' in [32*h2, 32*h2+32)  <=>  phl in {2*h2, 2*h2+1}
        // region: c in [0,3), hn in [0,14), phll in {0,1}, w in [0,224)
        // float4 index e4 in [0,4704): r = e4/56, w = 4*(e4%56)
        //   phll = r&1, hn = (r>>1)%14, c = r/28
        #pragma unroll 2
        for (int e4 = tid; e4 < 4704; e4 += THREADS) {
            int w4   = e4 % 56;
            int r    = e4 / 56;
            int w    = w4 << 2;
            int phll = r & 1;
            int r2   = r >> 1;
            int hn   = r2 % 14;
            int c    = r2 / 14;

            int h = hn * 16 + 4 * g + 2 * h2 + phll;
            float4 val = *(const float4*)(xb + ((size_t)c * 224 + h) * 224 + w);

            int pw = w & 15;              // 0,4,8,12 -> 4 lanes same wn
            int wn = w >> 4;
            int spl = phll * 16 + pw;     // local s' in [0,32)
            float* dst = &Y[spl * VPAD + c * 196 + hn * 14 + wn];
            dst[0 * VPAD] = val.x;
            dst[1 * VPAD] = val.y;
            dst[2 * VPAD] = val.z;
            dst[3 * VPAD] = val.w;
        }
        __syncthreads();

        // ---- Phase 2: dot segments inside this half's u' range ----
        const int rlo = HALF_U * h2, rhi = rlo + HALF_U;
        const int spoff = 32 * h2;

        #pragma unroll
        for (int i = 0; i < 4; i++) {
            int jl = warp + 16 * i;               // warp owns {w, w+16, w+32}
            if (i == 3) jl = 48;                  // extra row for warp 0
            if (i < 3 || warp == 0) {
                int ulo = max(768 * jl, rlo);
                int uhi = min(768 * jl + 768, rhi);
                float a = 0.f;
                for (int u = ulo + lane; u < uhi; u += 32) {
                    int sp = (unsigned)u / 588u;
                    int v  = u - sp * 588;
                    a += Ws[u - 768 * jl] * Y[(sp - spoff) * VPAD + v];
                }
                if (i == 0) acc0 += a;
                else if (i == 1) acc1 += a;
                else if (i == 2) acc2 += a;
                else acc3 += a;
            }
        }
    }

    // ---- final warp reductions + store ----
    const float bv = __ldg(bias);
    float accs[4] = {acc0, acc1, acc2, acc3};
    #pragma unroll
    for (int i = 0; i < 4; i++) {
        int jl = warp + 16 * i;
        if (i == 3) jl = 48;
        if (i < 3 || warp == 0) {
            float a = accs[i];
            #pragma unroll
            for (int off = 16; off; off >>= 1)
                a += __shfl_xor_sync(0xffffffffu, a, off);
            if (lane == 0)
                out[b * 196 + 49 * g + jl] = a + bv;
        }
    }
}

extern "C" void kernel_launch(void* const* d_in, const int* in_sizes, int n_in,
                              void* d_out, int out_size)
{
    const float* x  = (const float*)d_in[0];
    const float* W  = (const float*)d_in[1];
    const float* bb = (const float*)d_in[2];
    float* out = (float*)d_out;

    const int smem_bytes = (32 * VPAD + 768) * sizeof(float);  // ~78.5 KB
    cudaFuncSetAttribute(patch_scorer_v3,
                         cudaFuncAttributeMaxDynamicSharedMemorySize, smem_bytes);

    patch_scorer_v3<<<512 * 4, THREADS, smem_bytes>>>(x, W, bb, out);
}